// round 7
// baseline (speedup 1.0000x reference)
#include <cuda_runtime.h>
#include <cstdint>
#include <math.h>

#define N_NODES 100000
#define N_EDGES 1600000
#define F_IN    256
#define HID     64

// -------- scratch (no device allocations allowed) --------
__device__ int   g_degi  [N_NODES];
__device__ float g_dinv  [N_NODES];
__device__ int   g_rstart[N_NODES];
__device__ int   g_cursor[N_NODES];
__device__ int   g_bsum  [512];
__device__ int   g_csr   [N_EDGES];
__device__ float g_h     [(size_t)N_NODES * HID];
__device__ float g_x2    [(size_t)N_NODES * HID];
__device__ float g_h3    [(size_t)N_NODES * 2];

// -------------------- degree --------------------
__global__ void k_zero_deg(int* __restrict__ deg, int n) {
    int i = blockIdx.x * blockDim.x + threadIdx.x;
    if (i < n) deg[i] = 0;
}

__global__ void k_count_deg(const int* __restrict__ dst, int* __restrict__ deg, int e) {
    int i = blockIdx.x * blockDim.x + threadIdx.x;
    if (i < e) atomicAdd(&deg[dst[i]], 1);
}

// -------------------- two-level exclusive scan over deg --------------------
__global__ void k_scan_block(const int* __restrict__ deg, int* __restrict__ rstart,
                             int* __restrict__ bsum, int n) {
    __shared__ int sm[256];
    int i = blockIdx.x * 256 + threadIdx.x;
    int v = (i < n) ? deg[i] : 0;
    sm[threadIdx.x] = v;
    __syncthreads();
    #pragma unroll
    for (int off = 1; off < 256; off <<= 1) {
        int t = (threadIdx.x >= off) ? sm[threadIdx.x - off] : 0;
        __syncthreads();
        sm[threadIdx.x] += t;
        __syncthreads();
    }
    if (i < n) rstart[i] = sm[threadIdx.x] - v;       // exclusive
    if (threadIdx.x == 255) bsum[blockIdx.x] = sm[255];
}

__global__ void k_scan_sums(int* __restrict__ bsum, int nb) {   // 1 block, 512 threads
    __shared__ int sm[512];
    int v = (threadIdx.x < nb) ? bsum[threadIdx.x] : 0;
    sm[threadIdx.x] = v;
    __syncthreads();
    #pragma unroll
    for (int off = 1; off < 512; off <<= 1) {
        int t = (threadIdx.x >= off) ? sm[threadIdx.x - off] : 0;
        __syncthreads();
        sm[threadIdx.x] += t;
        __syncthreads();
    }
    if (threadIdx.x < nb) bsum[threadIdx.x] = sm[threadIdx.x] - v;  // exclusive
}

// add block offsets + init cursor + compute dinv (fused)
__global__ void k_add_off(int* __restrict__ rstart, int* __restrict__ cursor,
                          const int* __restrict__ bsum, const int* __restrict__ degi,
                          float* __restrict__ dinv, int n) {
    int i = blockIdx.x * blockDim.x + threadIdx.x;
    if (i < n) {
        int v = rstart[i] + bsum[i >> 8];
        rstart[i] = v;
        cursor[i] = v;
        dinv[i] = rsqrtf((float)(degi[i] + 1));   // +1 self-loop
    }
}

__global__ void k_build_csr(const int* __restrict__ src, const int* __restrict__ dst,
                            int* __restrict__ cursor, int* __restrict__ csr, int e) {
    int i = blockIdx.x * blockDim.x + threadIdx.x;
    if (i < e) {
        int p = atomicAdd(&cursor[dst[i]], 1);
        csr[p] = src[i];
    }
}

// -------------------- tf32 tensor-core GEMM, cp.async double-buffered ------------------
// out[m,0:64] = (A[m,:]@W) * (SCALED ? dinv[m] : 1)
// BM=128, BN=64, BK=32; 256 threads = 8 warps (4 M x 2 N), warp tile 32x32.
// mma.sync.m16n8k8 tf32 (raw fp32 bits, truncated), fp32 accumulate.
// Dynamic smem: A0[4608] A1[4608] B0[2304] B1[2304] words = 55296 bytes.
#define SMEM_WORDS_A 4608   // 128*36
#define SMEM_WORDS_B 2304   // 32*72
#define GEMM_TC_SMEM ((2 * (SMEM_WORDS_A + SMEM_WORDS_B)) * 4)

template <int K, bool SCALED>
__global__ __launch_bounds__(256) void k_gemm_tc(
        const float* __restrict__ A, const float* __restrict__ W,
        const float* __restrict__ dinv, float* __restrict__ out, int M) {
    extern __shared__ uint32_t smem[];
    uint32_t* sA0 = smem;
    uint32_t* sA1 = smem + SMEM_WORDS_A;
    uint32_t* sB0 = smem + 2 * SMEM_WORDS_A;
    uint32_t* sB1 = smem + 2 * SMEM_WORDS_A + SMEM_WORDS_B;

    const int tid  = threadIdx.x;
    const int lane = tid & 31;
    const int warp = tid >> 5;
    const int wm   = warp & 3;         // M warp 0..3 (32 rows each)
    const int wn   = warp >> 2;        // N warp 0..1 (32 cols each)
    const int g    = lane >> 2;        // groupID 0..7
    const int t    = lane & 3;         // thread-in-group 0..3
    const int row0 = blockIdx.x * 128;

    // per-thread cp.async chunk coordinates
    int am[4], ac[4];
    #pragma unroll
    for (int l = 0; l < 4; l++) {
        int i = tid + l * 256;          // 0..1023 16B chunks of A tile
        am[l] = i >> 3;                 // row 0..127
        ac[l] = (i & 7) << 2;           // col word 0,4,..,28
    }
    int bkk[2], bc[2];
    #pragma unroll
    for (int l = 0; l < 2; l++) {
        int i = tid + l * 256;          // 0..511 16B chunks of B tile
        bkk[l] = i >> 4;                // k row 0..31
        bc[l]  = (i & 15) << 2;         // n word 0,4,..,60
    }

    float c[2][4][4] = {};

    // ---- prefetch tile 0 ----
    {
        #pragma unroll
        for (int l = 0; l < 4; l++) {
            int gr = row0 + am[l];
            const float* src = A + (size_t)(gr < M ? gr : (M - 1)) * K + ac[l];
            uint32_t d = (uint32_t)__cvta_generic_to_shared(sA0 + am[l] * 36 + ac[l]);
            int sz = (gr < M) ? 16 : 0;
            asm volatile("cp.async.cg.shared.global [%0], [%1], 16, %2;" :: "r"(d), "l"(src), "r"(sz));
        }
        #pragma unroll
        for (int l = 0; l < 2; l++) {
            const float* src = W + (size_t)bkk[l] * 64 + bc[l];
            uint32_t d = (uint32_t)__cvta_generic_to_shared(sB0 + bkk[l] * 72 + bc[l]);
            asm volatile("cp.async.cg.shared.global [%0], [%1], 16;" :: "r"(d), "l"(src));
        }
        asm volatile("cp.async.commit_group;");
    }

    constexpr int NT = K / 32;
    #pragma unroll
    for (int kt = 0; kt < NT; kt++) {
        uint32_t* cA = (kt & 1) ? sA1 : sA0;
        uint32_t* cB = (kt & 1) ? sB1 : sB0;

        if (kt + 1 < NT) {
            // prefetch next tile into alternate buffer
            uint32_t* nA = (kt & 1) ? sA0 : sA1;
            uint32_t* nB = (kt & 1) ? sB0 : sB1;
            int k0 = (kt + 1) * 32;
            #pragma unroll
            for (int l = 0; l < 4; l++) {
                int gr = row0 + am[l];
                const float* src = A + (size_t)(gr < M ? gr : (M - 1)) * K + k0 + ac[l];
                uint32_t d = (uint32_t)__cvta_generic_to_shared(nA + am[l] * 36 + ac[l]);
                int sz = (gr < M) ? 16 : 0;
                asm volatile("cp.async.cg.shared.global [%0], [%1], 16, %2;" :: "r"(d), "l"(src), "r"(sz));
            }
            #pragma unroll
            for (int l = 0; l < 2; l++) {
                const float* src = W + (size_t)(k0 + bkk[l]) * 64 + bc[l];
                uint32_t d = (uint32_t)__cvta_generic_to_shared(nB + bkk[l] * 72 + bc[l]);
                asm volatile("cp.async.cg.shared.global [%0], [%1], 16;" :: "r"(d), "l"(src));
            }
            asm volatile("cp.async.commit_group;");
            asm volatile("cp.async.wait_group 1;");   // current tile complete
        } else {
            asm volatile("cp.async.wait_group 0;");
        }
        __syncthreads();

        #pragma unroll
        for (int kc = 0; kc < 4; kc++) {
            int kb = kc * 8;
            uint32_t a[2][4];
            #pragma unroll
            for (int mt = 0; mt < 2; mt++) {
                int mb = wm * 32 + mt * 16;
                a[mt][0] = cA[(mb + g    ) * 36 + kb + t    ];
                a[mt][1] = cA[(mb + g + 8) * 36 + kb + t    ];
                a[mt][2] = cA[(mb + g    ) * 36 + kb + t + 4];
                a[mt][3] = cA[(mb + g + 8) * 36 + kb + t + 4];
            }
            uint32_t bfr[4][2];
            #pragma unroll
            for (int j = 0; j < 4; j++) {
                int nb = wn * 32 + j * 8;
                bfr[j][0] = cB[(kb + t    ) * 72 + nb + g];
                bfr[j][1] = cB[(kb + t + 4) * 72 + nb + g];
            }
            #pragma unroll
            for (int mt = 0; mt < 2; mt++) {
                #pragma unroll
                for (int j = 0; j < 4; j++) {
                    asm volatile(
                        "mma.sync.aligned.m16n8k8.row.col.f32.tf32.tf32.f32 "
                        "{%0,%1,%2,%3}, {%4,%5,%6,%7}, {%8,%9}, {%0,%1,%2,%3};"
                        : "+f"(c[mt][j][0]), "+f"(c[mt][j][1]),
                          "+f"(c[mt][j][2]), "+f"(c[mt][j][3])
                        : "r"(a[mt][0]), "r"(a[mt][1]), "r"(a[mt][2]), "r"(a[mt][3]),
                          "r"(bfr[j][0]), "r"(bfr[j][1]));
                }
            }
        }
        __syncthreads();
    }

    // epilogue: c0,c1 -> row g; c2,c3 -> row g+8; cols 2t, 2t+1
    #pragma unroll
    for (int mt = 0; mt < 2; mt++) {
        int r0 = row0 + wm * 32 + mt * 16 + g;
        float d0 = (SCALED && r0 < M)     ? dinv[r0]     : 1.0f;
        float d1 = (SCALED && r0 + 8 < M) ? dinv[r0 + 8] : 1.0f;
        #pragma unroll
        for (int j = 0; j < 4; j++) {
            int col = wn * 32 + j * 8 + 2 * t;
            if (r0 < M)
                *(float2*)(out + (size_t)r0 * 64 + col) =
                    make_float2(c[mt][j][0] * d0, c[mt][j][1] * d0);
            if (r0 + 8 < M)
                *(float2*)(out + (size_t)(r0 + 8) * 64 + col) =
                    make_float2(c[mt][j][2] * d1, c[mt][j][3] * d1);
        }
    }
}

// -------------------- pull aggregation + fused epilogue (64 features) --------------------
// 16 threads per node, 4 features each; 4 independent gathers in flight.
// NSCALE=true: table h is UNSCALED (layer 1): neighbor rows scaled by dinv[u], self by dinv[node].
template <bool NSCALE>
__global__ void k_pull64(const int* __restrict__ rstart, const int* __restrict__ degi,
                         const int* __restrict__ csr, const float* __restrict__ h,
                         const float* __restrict__ dinv, const float* __restrict__ b,
                         float* __restrict__ out, int n) {
    int gid  = blockIdx.x * blockDim.x + threadIdx.x;
    int node = gid >> 4;
    if (node >= n) return;
    int c = (gid & 15) << 2;

    int s0  = __ldg(&rstart[node]);
    int cnt = __ldg(&degi[node]);
    float dn = dinv[node];

    float4 acc = *(const float4*)(h + (size_t)node * 64 + c);   // self-loop term
    if (NSCALE) { acc.x *= dn; acc.y *= dn; acc.z *= dn; acc.w *= dn; }

    int e = 0;
    for (; e + 4 <= cnt; e += 4) {
        int u0 = __ldg(&csr[s0 + e + 0]);
        int u1 = __ldg(&csr[s0 + e + 1]);
        int u2 = __ldg(&csr[s0 + e + 2]);
        int u3 = __ldg(&csr[s0 + e + 3]);
        float4 v0 = *(const float4*)(h + (size_t)u0 * 64 + c);
        float4 v1 = *(const float4*)(h + (size_t)u1 * 64 + c);
        float4 v2 = *(const float4*)(h + (size_t)u2 * 64 + c);
        float4 v3 = *(const float4*)(h + (size_t)u3 * 64 + c);
        if (NSCALE) {
            float d0 = __ldg(&dinv[u0]), d1 = __ldg(&dinv[u1]);
            float d2 = __ldg(&dinv[u2]), d3 = __ldg(&dinv[u3]);
            acc.x += v0.x * d0 + v1.x * d1 + v2.x * d2 + v3.x * d3;
            acc.y += v0.y * d0 + v1.y * d1 + v2.y * d2 + v3.y * d3;
            acc.z += v0.z * d0 + v1.z * d1 + v2.z * d2 + v3.z * d3;
            acc.w += v0.w * d0 + v1.w * d1 + v2.w * d2 + v3.w * d3;
        } else {
            acc.x += v0.x + v1.x + v2.x + v3.x;
            acc.y += v0.y + v1.y + v2.y + v3.y;
            acc.z += v0.z + v1.z + v2.z + v3.z;
            acc.w += v0.w + v1.w + v2.w + v3.w;
        }
    }
    for (; e < cnt; e++) {
        int u = __ldg(&csr[s0 + e]);
        float4 v = *(const float4*)(h + (size_t)u * 64 + c);
        float d = NSCALE ? __ldg(&dinv[u]) : 1.0f;
        acc.x += v.x * d; acc.y += v.y * d; acc.z += v.z * d; acc.w += v.w * d;
    }

    float4 bb = *(const float4*)(b + c);
    float4 o;
    o.x = fmaxf(dn * acc.x + bb.x, 0.f);
    o.y = fmaxf(dn * acc.y + bb.y, 0.f);
    o.z = fmaxf(dn * acc.z + bb.z, 0.f);
    o.w = fmaxf(dn * acc.w + bb.w, 0.f);
    *(float4*)(out + (size_t)node * 64 + c) = o;
}

// -------------------- layer 3: h3'[m, 0:2] = (A[m,:] @ W3) * dinv[m] --------------------
__global__ void k_gemm3(const float* __restrict__ A, const float* __restrict__ W3,
                        const float* __restrict__ dinv, float* __restrict__ out, int M) {
    __shared__ float w[128];
    if (threadIdx.x < 128) w[threadIdx.x] = W3[threadIdx.x];
    __syncthreads();
    int r = blockIdx.x * blockDim.x + threadIdx.x;
    if (r >= M) return;
    const float* ap = A + (size_t)r * 64;
    float a0 = 0.f, a1 = 0.f;
    #pragma unroll
    for (int k4 = 0; k4 < 64; k4 += 4) {
        float4 a = *(const float4*)(ap + k4);
        a0 += a.x * w[2 * k4 + 0] + a.y * w[2 * k4 + 2] + a.z * w[2 * k4 + 4] + a.w * w[2 * k4 + 6];
        a1 += a.x * w[2 * k4 + 1] + a.y * w[2 * k4 + 3] + a.z * w[2 * k4 + 5] + a.w * w[2 * k4 + 7];
    }
    float d = dinv[r];
    out[2 * r + 0] = a0 * d;
    out[2 * r + 1] = a1 * d;
}

// -------------------- layer 3: pull (2 feats) + log_softmax, 1 thread/node --------------------
__global__ void k_pull2_final(const int* __restrict__ rstart, const int* __restrict__ degi,
                              const int* __restrict__ csr, const float* __restrict__ h3,
                              const float* __restrict__ dinv, const float* __restrict__ b3,
                              float* __restrict__ out, int n) {
    int i = blockIdx.x * blockDim.x + threadIdx.x;
    if (i >= n) return;
    int s0  = __ldg(&rstart[i]);
    int cnt = __ldg(&degi[i]);

    float2 self = *(const float2*)(h3 + (size_t)i * 2);
    float a0 = self.x, a1 = self.y;

    int e = 0;
    for (; e + 4 <= cnt; e += 4) {
        int u0 = __ldg(&csr[s0 + e + 0]);
        int u1 = __ldg(&csr[s0 + e + 1]);
        int u2 = __ldg(&csr[s0 + e + 2]);
        int u3 = __ldg(&csr[s0 + e + 3]);
        float2 v0 = *(const float2*)(h3 + (size_t)u0 * 2);
        float2 v1 = *(const float2*)(h3 + (size_t)u1 * 2);
        float2 v2 = *(const float2*)(h3 + (size_t)u2 * 2);
        float2 v3 = *(const float2*)(h3 + (size_t)u3 * 2);
        a0 += v0.x + v1.x + v2.x + v3.x;
        a1 += v0.y + v1.y + v2.y + v3.y;
    }
    for (; e < cnt; e++) {
        int u = __ldg(&csr[s0 + e]);
        float2 v = *(const float2*)(h3 + (size_t)u * 2);
        a0 += v.x; a1 += v.y;
    }

    float d  = dinv[i];
    float o0 = d * a0 + b3[0];
    float o1 = d * a1 + b3[1];
    float m  = fmaxf(o0, o1);
    float lse = m + logf(expf(o0 - m) + expf(o1 - m));
    out[2 * i + 0] = o0 - lse;
    out[2 * i + 1] = o1 - lse;
}

// -------------------- launch --------------------
extern "C" void kernel_launch(void* const* d_in, const int* in_sizes, int n_in,
                              void* d_out, int out_size) {
    const float* x  = (const float*)d_in[0];
    const int*   ei = (const int*)  d_in[1];
    const float* W1 = (const float*)d_in[2];
    const float* b1 = (const float*)d_in[3];
    const float* W2 = (const float*)d_in[4];
    const float* b2 = (const float*)d_in[5];
    const float* W3 = (const float*)d_in[6];
    const float* b3 = (const float*)d_in[7];

    const int N = in_sizes[0] / F_IN;
    const int E = in_sizes[1] / 2;
    const int* src = ei;
    const int* dst = ei + E;

    int *degi, *rstart, *cursor, *bsum, *csr;
    float *dinv, *h, *x2, *h3;
    cudaGetSymbolAddress((void**)&degi,   g_degi);
    cudaGetSymbolAddress((void**)&rstart, g_rstart);
    cudaGetSymbolAddress((void**)&cursor, g_cursor);
    cudaGetSymbolAddress((void**)&bsum,   g_bsum);
    cudaGetSymbolAddress((void**)&csr,    g_csr);
    cudaGetSymbolAddress((void**)&dinv,   g_dinv);
    cudaGetSymbolAddress((void**)&h,      g_h);
    cudaGetSymbolAddress((void**)&x2,     g_x2);
    cudaGetSymbolAddress((void**)&h3,     g_h3);

    // First call = uncaptured correctness run: create side stream/events and
    // opt the tc-GEMM kernels into >48KB dynamic smem. Idempotent thereafter.
    static bool s_init = false, s_ok = false;
    static cudaStream_t s_side = nullptr;
    static cudaEvent_t  s_evA = nullptr, s_evB = nullptr;
    if (!s_init) {
        s_init = true;
        cudaFuncSetAttribute(k_gemm_tc<F_IN, false>,
                             cudaFuncAttributeMaxDynamicSharedMemorySize, GEMM_TC_SMEM);
        cudaFuncSetAttribute(k_gemm_tc<HID, true>,
                             cudaFuncAttributeMaxDynamicSharedMemorySize, GEMM_TC_SMEM);
        s_ok = (cudaStreamCreateWithFlags(&s_side, cudaStreamNonBlocking) == cudaSuccess) &&
               (cudaEventCreateWithFlags(&s_evA, cudaEventDisableTiming) == cudaSuccess) &&
               (cudaEventCreateWithFlags(&s_evB, cudaEventDisableTiming) == cudaSuccess);
    }

    const int T  = 256;
    const int NB = (N + 255) / 256;
    const int gemm_blocks = (N + 127) / 128;
    const int pull_blocks = (N * 16 + T - 1) / T;

    const bool fork = s_ok;
    cudaStream_t sp = fork ? s_side : (cudaStream_t)0;   // prep stream
    cudaStream_t ms = (cudaStream_t)0;                   // main stream

    if (fork) {
        cudaEventRecord(s_evA, ms);
        cudaStreamWaitEvent(sp, s_evA, 0);
    }

    // preprocessing on side stream (runs concurrently with layer-1 GEMM)
    k_zero_deg  <<<(N + T - 1) / T, T, 0, sp>>>(degi, N);
    k_count_deg <<<(E + T - 1) / T, T, 0, sp>>>(dst, degi, E);
    k_scan_block<<<NB, 256, 0, sp>>>(degi, rstart, bsum, N);

    // layer-1 GEMM (tf32 tc, cp.async pipelined, UNSCALED) — submission 4 = ncu slot
    k_gemm_tc<F_IN, false><<<gemm_blocks, T, GEMM_TC_SMEM, ms>>>(x, W1, nullptr, h, N);

    // preprocessing finish
    k_scan_sums <<<1, 512, 0, sp>>>(bsum, NB);
    k_add_off   <<<(N + T - 1) / T, T, 0, sp>>>(rstart, cursor, bsum, degi, dinv, N);
    k_build_csr <<<(E + T - 1) / T, T, 0, sp>>>(src, dst, cursor, csr, E);

    if (fork) {
        cudaEventRecord(s_evB, sp);
        cudaStreamWaitEvent(ms, s_evB, 0);
    }

    // ---- layer 1 aggregation (neighbor-scaled pull, since h is unscaled) ----
    k_pull64<true><<<pull_blocks, T, 0, ms>>>(rstart, degi, csr, h, dinv, b1, x2, N);

    // ---- layer 2 (tf32 tc, dinv-scaled epilogue) ----
    k_gemm_tc<HID, true><<<gemm_blocks, T, GEMM_TC_SMEM, ms>>>(x2, W2, dinv, h, N);
    k_pull64<false><<<pull_blocks, T, 0, ms>>>(rstart, degi, csr, h, dinv, b2, x2, N);

    // ---- layer 3 ----
    k_gemm3      <<<(N + T - 1) / T, T, 0, ms>>>(x2, W3, dinv, h3, N);
    k_pull2_final<<<(N + T - 1) / T, T, 0, ms>>>(rstart, degi, csr, h3, dinv, b3, (float*)d_out, N);
}

// round 8
// speedup vs baseline: 1.2052x; 1.2052x over previous
#include <cuda_runtime.h>
#include <cstdint>
#include <math.h>

#define N_NODES 100000
#define N_EDGES 1600000
#define F_IN    256
#define HID     64

// -------- scratch (no device allocations allowed) --------
__device__ int   g_degi  [N_NODES];
__device__ float g_dinv  [N_NODES];
__device__ int   g_rstart[N_NODES];
__device__ int   g_cursor[N_NODES];
__device__ int   g_bsum  [512];
__device__ int   g_csr   [N_EDGES];
__device__ float g_h     [(size_t)N_NODES * HID];
__device__ float g_x2    [(size_t)N_NODES * HID];
__device__ float g_h3    [(size_t)N_NODES * 2];

// -------------------- degree --------------------
__global__ void k_zero_deg(int* __restrict__ deg, int n) {
    int i = blockIdx.x * blockDim.x + threadIdx.x;
    if (i < n) deg[i] = 0;
}

__global__ void k_count_deg(const int* __restrict__ dst, int* __restrict__ deg, int e) {
    int i = blockIdx.x * blockDim.x + threadIdx.x;
    if (i < e) atomicAdd(&deg[dst[i]], 1);
}

// -------------------- two-level exclusive scan over deg --------------------
__global__ void k_scan_block(const int* __restrict__ deg, int* __restrict__ rstart,
                             int* __restrict__ bsum, int n) {
    __shared__ int sm[256];
    int i = blockIdx.x * 256 + threadIdx.x;
    int v = (i < n) ? deg[i] : 0;
    sm[threadIdx.x] = v;
    __syncthreads();
    #pragma unroll
    for (int off = 1; off < 256; off <<= 1) {
        int t = (threadIdx.x >= off) ? sm[threadIdx.x - off] : 0;
        __syncthreads();
        sm[threadIdx.x] += t;
        __syncthreads();
    }
    if (i < n) rstart[i] = sm[threadIdx.x] - v;       // exclusive
    if (threadIdx.x == 255) bsum[blockIdx.x] = sm[255];
}

__global__ void k_scan_sums(int* __restrict__ bsum, int nb) {   // 1 block, 512 threads
    __shared__ int sm[512];
    int v = (threadIdx.x < nb) ? bsum[threadIdx.x] : 0;
    sm[threadIdx.x] = v;
    __syncthreads();
    #pragma unroll
    for (int off = 1; off < 512; off <<= 1) {
        int t = (threadIdx.x >= off) ? sm[threadIdx.x - off] : 0;
        __syncthreads();
        sm[threadIdx.x] += t;
        __syncthreads();
    }
    if (threadIdx.x < nb) bsum[threadIdx.x] = sm[threadIdx.x] - v;  // exclusive
}

// add block offsets + init cursor + compute dinv (fused)
__global__ void k_add_off(int* __restrict__ rstart, int* __restrict__ cursor,
                          const int* __restrict__ bsum, const int* __restrict__ degi,
                          float* __restrict__ dinv, int n) {
    int i = blockIdx.x * blockDim.x + threadIdx.x;
    if (i < n) {
        int v = rstart[i] + bsum[i >> 8];
        rstart[i] = v;
        cursor[i] = v;
        dinv[i] = rsqrtf((float)(degi[i] + 1));   // +1 self-loop
    }
}

__global__ void k_build_csr(const int* __restrict__ src, const int* __restrict__ dst,
                            int* __restrict__ cursor, int* __restrict__ csr, int e) {
    int i = blockIdx.x * blockDim.x + threadIdx.x;
    if (i < e) {
        int p = atomicAdd(&cursor[dst[i]], 1);
        csr[p] = src[i];
    }
}

// -------------------- helpers for tf32 MMA --------------------
__device__ __forceinline__ uint32_t f2tf32(float f) {
    uint32_t u;
    asm("cvt.rna.tf32.f32 %0, %1;" : "=r"(u) : "f"(f));
    return u;
}

// -------------------- tf32 tensor-core GEMM (R6-proven): out = (A@W) * (SCALED?dinv:1) ---
// BM=128, BN=64, BK=32; 256 threads = 8 warps (4 M x 2 N), warp tile 32x32.
// mma.sync.m16n8k8 tf32 (cvt.rna rounding), fp32 accumulate. Static smem.
template <int K, bool SCALED>
__global__ __launch_bounds__(256) void k_gemm_tc(
        const float* __restrict__ A, const float* __restrict__ W,
        const float* __restrict__ dinv, float* __restrict__ out, int M) {
    __shared__ uint32_t As[128][36];   // [m][k], stride 36: conflict-free frags
    __shared__ uint32_t Bs[32][72];    // [k][n], stride 72: conflict-free frags

    const int tid  = threadIdx.x;
    const int lane = tid & 31;
    const int warp = tid >> 5;
    const int wm   = warp & 3;         // M warp 0..3 (32 rows each)
    const int wn   = warp >> 2;        // N warp 0..1 (32 cols each)
    const int g    = lane >> 2;        // groupID 0..7
    const int t    = lane & 3;         // thread-in-group 0..3
    const int row0 = blockIdx.x * 128;

    float c[2][4][4] = {};             // [m-tile 16][n-tile 8][frag]

    for (int k0 = 0; k0 < K; k0 += 32) {
        // ---- A tile 128x32 -> tf32 smem ----
        #pragma unroll
        for (int l = 0; l < 4; l++) {
            int i  = tid + l * 256;      // 0..1023 float4 slots
            int m  = i >> 3;
            int kk = (i & 7) << 2;
            int gr = row0 + m;
            float4 v = (gr < M) ? *(const float4*)(A + (size_t)gr * K + k0 + kk)
                                : make_float4(0.f, 0.f, 0.f, 0.f);
            uint4 u = make_uint4(f2tf32(v.x), f2tf32(v.y), f2tf32(v.z), f2tf32(v.w));
            *(uint4*)&As[m][kk] = u;
        }
        // ---- B tile 32x64 -> tf32 smem ----
        #pragma unroll
        for (int l = 0; l < 2; l++) {
            int i  = tid + l * 256;
            int kk = i >> 4;
            int n  = (i & 15) << 2;
            float4 v = *(const float4*)(W + (size_t)(k0 + kk) * 64 + n);
            uint4 u = make_uint4(f2tf32(v.x), f2tf32(v.y), f2tf32(v.z), f2tf32(v.w));
            *(uint4*)&Bs[kk][n] = u;
        }
        __syncthreads();

        #pragma unroll
        for (int kc = 0; kc < 4; kc++) {
            int kb = kc * 8;
            uint32_t a[2][4];
            #pragma unroll
            for (int mt = 0; mt < 2; mt++) {
                int mb = wm * 32 + mt * 16;
                a[mt][0] = As[mb + g     ][kb + t    ];
                a[mt][1] = As[mb + g + 8 ][kb + t    ];
                a[mt][2] = As[mb + g     ][kb + t + 4];
                a[mt][3] = As[mb + g + 8 ][kb + t + 4];
            }
            uint32_t bfr[4][2];
            #pragma unroll
            for (int j = 0; j < 4; j++) {
                int nb = wn * 32 + j * 8;
                bfr[j][0] = Bs[kb + t    ][nb + g];
                bfr[j][1] = Bs[kb + t + 4][nb + g];
            }
            #pragma unroll
            for (int mt = 0; mt < 2; mt++) {
                #pragma unroll
                for (int j = 0; j < 4; j++) {
                    asm volatile(
                        "mma.sync.aligned.m16n8k8.row.col.f32.tf32.tf32.f32 "
                        "{%0,%1,%2,%3}, {%4,%5,%6,%7}, {%8,%9}, {%0,%1,%2,%3};"
                        : "+f"(c[mt][j][0]), "+f"(c[mt][j][1]),
                          "+f"(c[mt][j][2]), "+f"(c[mt][j][3])
                        : "r"(a[mt][0]), "r"(a[mt][1]), "r"(a[mt][2]), "r"(a[mt][3]),
                          "r"(bfr[j][0]), "r"(bfr[j][1]));
                }
            }
        }
        __syncthreads();
    }

    // epilogue: c0,c1 -> row g; c2,c3 -> row g+8; cols 2t, 2t+1
    #pragma unroll
    for (int mt = 0; mt < 2; mt++) {
        int r0 = row0 + wm * 32 + mt * 16 + g;
        float d0 = (SCALED && r0 < M)     ? dinv[r0]     : 1.0f;
        float d1 = (SCALED && r0 + 8 < M) ? dinv[r0 + 8] : 1.0f;
        #pragma unroll
        for (int j = 0; j < 4; j++) {
            int col = wn * 32 + j * 8 + 2 * t;
            if (r0 < M)
                *(float2*)(out + (size_t)r0 * 64 + col) =
                    make_float2(c[mt][j][0] * d0, c[mt][j][1] * d0);
            if (r0 + 8 < M)
                *(float2*)(out + (size_t)(r0 + 8) * 64 + col) =
                    make_float2(c[mt][j][2] * d1, c[mt][j][3] * d1);
        }
    }
}

// -------------------- pull aggregation + fused epilogue (64 features) --------------------
// 16 threads per node, 4 features each; 4 independent gathers in flight.
// NSCALE=true: table h is UNSCALED (layer 1): neighbor rows scaled by dinv[u], self by dinv[node].
template <bool NSCALE>
__global__ void k_pull64(const int* __restrict__ rstart, const int* __restrict__ degi,
                         const int* __restrict__ csr, const float* __restrict__ h,
                         const float* __restrict__ dinv, const float* __restrict__ b,
                         float* __restrict__ out, int n) {
    int gid  = blockIdx.x * blockDim.x + threadIdx.x;
    int node = gid >> 4;
    if (node >= n) return;
    int c = (gid & 15) << 2;

    int s0  = __ldg(&rstart[node]);
    int cnt = __ldg(&degi[node]);
    float dn = dinv[node];

    float4 acc = *(const float4*)(h + (size_t)node * 64 + c);   // self-loop term
    if (NSCALE) { acc.x *= dn; acc.y *= dn; acc.z *= dn; acc.w *= dn; }

    int e = 0;
    for (; e + 4 <= cnt; e += 4) {
        int u0 = __ldg(&csr[s0 + e + 0]);
        int u1 = __ldg(&csr[s0 + e + 1]);
        int u2 = __ldg(&csr[s0 + e + 2]);
        int u3 = __ldg(&csr[s0 + e + 3]);
        float4 v0 = *(const float4*)(h + (size_t)u0 * 64 + c);
        float4 v1 = *(const float4*)(h + (size_t)u1 * 64 + c);
        float4 v2 = *(const float4*)(h + (size_t)u2 * 64 + c);
        float4 v3 = *(const float4*)(h + (size_t)u3 * 64 + c);
        if (NSCALE) {
            float d0 = __ldg(&dinv[u0]), d1 = __ldg(&dinv[u1]);
            float d2 = __ldg(&dinv[u2]), d3 = __ldg(&dinv[u3]);
            acc.x += v0.x * d0 + v1.x * d1 + v2.x * d2 + v3.x * d3;
            acc.y += v0.y * d0 + v1.y * d1 + v2.y * d2 + v3.y * d3;
            acc.z += v0.z * d0 + v1.z * d1 + v2.z * d2 + v3.z * d3;
            acc.w += v0.w * d0 + v1.w * d1 + v2.w * d2 + v3.w * d3;
        } else {
            acc.x += v0.x + v1.x + v2.x + v3.x;
            acc.y += v0.y + v1.y + v2.y + v3.y;
            acc.z += v0.z + v1.z + v2.z + v3.z;
            acc.w += v0.w + v1.w + v2.w + v3.w;
        }
    }
    for (; e < cnt; e++) {
        int u = __ldg(&csr[s0 + e]);
        float4 v = *(const float4*)(h + (size_t)u * 64 + c);
        float d = NSCALE ? __ldg(&dinv[u]) : 1.0f;
        acc.x += v.x * d; acc.y += v.y * d; acc.z += v.z * d; acc.w += v.w * d;
    }

    float4 bb = *(const float4*)(b + c);
    float4 o;
    o.x = fmaxf(dn * acc.x + bb.x, 0.f);
    o.y = fmaxf(dn * acc.y + bb.y, 0.f);
    o.z = fmaxf(dn * acc.z + bb.z, 0.f);
    o.w = fmaxf(dn * acc.w + bb.w, 0.f);
    *(float4*)(out + (size_t)node * 64 + c) = o;
}

// -------------------- layer 3: h3'[m, 0:2] = (A[m,:] @ W3) * dinv[m] --------------------
__global__ void k_gemm3(const float* __restrict__ A, const float* __restrict__ W3,
                        const float* __restrict__ dinv, float* __restrict__ out, int M) {
    __shared__ float w[128];
    if (threadIdx.x < 128) w[threadIdx.x] = W3[threadIdx.x];
    __syncthreads();
    int r = blockIdx.x * blockDim.x + threadIdx.x;
    if (r >= M) return;
    const float* ap = A + (size_t)r * 64;
    float a0 = 0.f, a1 = 0.f;
    #pragma unroll
    for (int k4 = 0; k4 < 64; k4 += 4) {
        float4 a = *(const float4*)(ap + k4);
        a0 += a.x * w[2 * k4 + 0] + a.y * w[2 * k4 + 2] + a.z * w[2 * k4 + 4] + a.w * w[2 * k4 + 6];
        a1 += a.x * w[2 * k4 + 1] + a.y * w[2 * k4 + 3] + a.z * w[2 * k4 + 5] + a.w * w[2 * k4 + 7];
    }
    float d = dinv[r];
    out[2 * r + 0] = a0 * d;
    out[2 * r + 1] = a1 * d;
}

// -------------------- layer 3: pull (2 feats) + log_softmax, 1 thread/node --------------------
__global__ void k_pull2_final(const int* __restrict__ rstart, const int* __restrict__ degi,
                              const int* __restrict__ csr, const float* __restrict__ h3,
                              const float* __restrict__ dinv, const float* __restrict__ b3,
                              float* __restrict__ out, int n) {
    int i = blockIdx.x * blockDim.x + threadIdx.x;
    if (i >= n) return;
    int s0  = __ldg(&rstart[i]);
    int cnt = __ldg(&degi[i]);

    float2 self = *(const float2*)(h3 + (size_t)i * 2);
    float a0 = self.x, a1 = self.y;

    int e = 0;
    for (; e + 4 <= cnt; e += 4) {
        int u0 = __ldg(&csr[s0 + e + 0]);
        int u1 = __ldg(&csr[s0 + e + 1]);
        int u2 = __ldg(&csr[s0 + e + 2]);
        int u3 = __ldg(&csr[s0 + e + 3]);
        float2 v0 = *(const float2*)(h3 + (size_t)u0 * 2);
        float2 v1 = *(const float2*)(h3 + (size_t)u1 * 2);
        float2 v2 = *(const float2*)(h3 + (size_t)u2 * 2);
        float2 v3 = *(const float2*)(h3 + (size_t)u3 * 2);
        a0 += v0.x + v1.x + v2.x + v3.x;
        a1 += v0.y + v1.y + v2.y + v3.y;
    }
    for (; e < cnt; e++) {
        int u = __ldg(&csr[s0 + e]);
        float2 v = *(const float2*)(h3 + (size_t)u * 2);
        a0 += v.x; a1 += v.y;
    }

    float d  = dinv[i];
    float o0 = d * a0 + b3[0];
    float o1 = d * a1 + b3[1];
    float m  = fmaxf(o0, o1);
    float lse = m + logf(expf(o0 - m) + expf(o1 - m));
    out[2 * i + 0] = o0 - lse;
    out[2 * i + 1] = o1 - lse;
}

// -------------------- launch (single stream, serial) --------------------
extern "C" void kernel_launch(void* const* d_in, const int* in_sizes, int n_in,
                              void* d_out, int out_size) {
    const float* x  = (const float*)d_in[0];
    const int*   ei = (const int*)  d_in[1];
    const float* W1 = (const float*)d_in[2];
    const float* b1 = (const float*)d_in[3];
    const float* W2 = (const float*)d_in[4];
    const float* b2 = (const float*)d_in[5];
    const float* W3 = (const float*)d_in[6];
    const float* b3 = (const float*)d_in[7];

    const int N = in_sizes[0] / F_IN;
    const int E = in_sizes[1] / 2;
    const int* src = ei;
    const int* dst = ei + E;

    int *degi, *rstart, *cursor, *bsum, *csr;
    float *dinv, *h, *x2, *h3;
    cudaGetSymbolAddress((void**)&degi,   g_degi);
    cudaGetSymbolAddress((void**)&rstart, g_rstart);
    cudaGetSymbolAddress((void**)&cursor, g_cursor);
    cudaGetSymbolAddress((void**)&bsum,   g_bsum);
    cudaGetSymbolAddress((void**)&csr,    g_csr);
    cudaGetSymbolAddress((void**)&dinv,   g_dinv);
    cudaGetSymbolAddress((void**)&h,      g_h);
    cudaGetSymbolAddress((void**)&x2,     g_x2);
    cudaGetSymbolAddress((void**)&h3,     g_h3);

    const int T  = 256;
    const int NB = (N + 255) / 256;
    const int gemm_blocks = (N + 127) / 128;
    const int pull_blocks = (N * 16 + T - 1) / T;

    // prep start (independent of gemm1)
    k_zero_deg  <<<(N + T - 1) / T, T>>>(degi, N);
    k_count_deg <<<(E + T - 1) / T, T>>>(dst, degi, E);
    k_scan_block<<<NB, 256>>>(degi, rstart, bsum, N);

    // layer-1 GEMM (tf32 tc, UNSCALED) — submission 4 = ncu slot
    k_gemm_tc<F_IN, false><<<gemm_blocks, T>>>(x, W1, nullptr, h, N);

    // prep finish
    k_scan_sums <<<1, 512>>>(bsum, NB);
    k_add_off   <<<(N + T - 1) / T, T>>>(rstart, cursor, bsum, degi, dinv, N);
    k_build_csr <<<(E + T - 1) / T, T>>>(src, dst, cursor, csr, E);

    // ---- layer 1 aggregation (neighbor-scaled pull, since h is unscaled) ----
    k_pull64<true><<<pull_blocks, T>>>(rstart, degi, csr, h, dinv, b1, x2, N);

    // ---- layer 2 (tf32 tc, dinv-scaled epilogue) ----
    k_gemm_tc<HID, true><<<gemm_blocks, T>>>(x2, W2, dinv, h, N);
    k_pull64<false><<<pull_blocks, T>>>(rstart, degi, csr, h, dinv, b2, x2, N);

    // ---- layer 3 ----
    k_gemm3      <<<(N + T - 1) / T, T>>>(x2, W3, dinv, h3, N);
    k_pull2_final<<<(N + T - 1) / T, T>>>(rstart, degi, csr, h3, dinv, b3, (float*)d_out, N);
}

// round 9
// speedup vs baseline: 1.3371x; 1.1095x over previous
#include <cuda_runtime.h>
#include <cstdint>
#include <math.h>

#define N_NODES 100000
#define N_EDGES 1600000
#define F_IN    256
#define HID     64

// -------- scratch (no device allocations allowed) --------
__device__ int   g_degi  [N_NODES];
__device__ float g_dinv  [N_NODES];
__device__ int   g_rstart[N_NODES];
__device__ int   g_cursor[N_NODES];
__device__ int   g_bsum  [512];
__device__ int   g_csr   [N_EDGES];
__device__ float g_h     [(size_t)N_NODES * HID];
__device__ float g_x2    [(size_t)N_NODES * HID];
__device__ float g_h3    [(size_t)N_NODES * 2];

// -------------------- degree --------------------
__global__ void k_zero_deg(int* __restrict__ deg, int n) {
    int i = blockIdx.x * blockDim.x + threadIdx.x;
    if (i < n) deg[i] = 0;
}

__global__ void k_count_deg(const int* __restrict__ dst, int* __restrict__ deg, int e) {
    int i = blockIdx.x * blockDim.x + threadIdx.x;
    if (i < e) atomicAdd(&deg[dst[i]], 1);
}

// -------------------- block-level exclusive scan over deg --------------------
// bsum[b] = total of block b (raw, NOT scanned)
__global__ void k_scan_block(const int* __restrict__ deg, int* __restrict__ rstart,
                             int* __restrict__ bsum, int n) {
    __shared__ int sm[256];
    int i = blockIdx.x * 256 + threadIdx.x;
    int v = (i < n) ? deg[i] : 0;
    sm[threadIdx.x] = v;
    __syncthreads();
    #pragma unroll
    for (int off = 1; off < 256; off <<= 1) {
        int t = (threadIdx.x >= off) ? sm[threadIdx.x - off] : 0;
        __syncthreads();
        sm[threadIdx.x] += t;
        __syncthreads();
    }
    if (i < n) rstart[i] = sm[threadIdx.x] - v;       // exclusive within block
    if (threadIdx.x == 255) bsum[blockIdx.x] = sm[255];
}

// add per-block global offset (reduced from raw bsum) + init cursor + dinv (fused)
__global__ void k_add_off(int* __restrict__ rstart, int* __restrict__ cursor,
                          const int* __restrict__ bsum, const int* __restrict__ degi,
                          float* __restrict__ dinv, int n) {
    __shared__ int sm[256];
    int b = blockIdx.x;
    int t = threadIdx.x;
    // sum of bsum[0..b)
    int v = 0;
    for (int j = t; j < b; j += 256) v += bsum[j];
    sm[t] = v;
    __syncthreads();
    #pragma unroll
    for (int off = 128; off > 0; off >>= 1) {
        if (t < off) sm[t] += sm[t + off];
        __syncthreads();
    }
    int off0 = sm[0];
    int i = b * 256 + t;
    if (i < n) {
        int val = rstart[i] + off0;
        rstart[i] = val;
        cursor[i] = val;
        dinv[i] = rsqrtf((float)(degi[i] + 1));   // +1 self-loop
    }
}

__global__ void k_build_csr(const int* __restrict__ src, const int* __restrict__ dst,
                            int* __restrict__ cursor, int* __restrict__ csr, int e) {
    int i = blockIdx.x * blockDim.x + threadIdx.x;
    if (i < e) {
        int p = atomicAdd(&cursor[dst[i]], 1);
        csr[p] = src[i];
    }
}

// -------------------- helpers for tf32 MMA --------------------
__device__ __forceinline__ uint32_t f2tf32(float f) {
    uint32_t u;
    asm("cvt.rna.tf32.f32 %0, %1;" : "=r"(u) : "f"(f));
    return u;
}
__device__ __forceinline__ uint4 cvt4(float4 v) {
    return make_uint4(f2tf32(v.x), f2tf32(v.y), f2tf32(v.z), f2tf32(v.w));
}

// -------------------- tf32 tensor-core GEMM with register prefetch ----------------------
// out[m,0:64] = (A[m,:]@W) * (SCALED ? dinv[m] : 1)
// BM=128, BN=64, BK=32; 256 threads = 8 warps (4 M x 2 N), warp tile 32x32.
// Static smem; next k-tile LDG issued before the MMA block (overlaps ~600cy gmem latency).
template <int K, bool SCALED>
__global__ __launch_bounds__(256) void k_gemm_tc(
        const float* __restrict__ A, const float* __restrict__ W,
        const float* __restrict__ dinv, float* __restrict__ out, int M) {
    __shared__ uint32_t As[128][36];   // [m][k], stride 36: conflict-free frags
    __shared__ uint32_t Bs[32][72];    // [k][n], stride 72: conflict-free frags

    const int tid  = threadIdx.x;
    const int lane = tid & 31;
    const int warp = tid >> 5;
    const int wm   = warp & 3;         // M warp 0..3 (32 rows each)
    const int wn   = warp >> 2;        // N warp 0..1 (32 cols each)
    const int g    = lane >> 2;        // groupID 0..7
    const int t    = lane & 3;         // thread-in-group 0..3
    const int row0 = blockIdx.x * 128;

    int am[4], ak[4];
    #pragma unroll
    for (int l = 0; l < 4; l++) {
        int i = tid + l * 256;          // 0..1023 float4 slots of A tile
        am[l] = i >> 3;
        ak[l] = (i & 7) << 2;
    }
    int bk[2], bn[2];
    #pragma unroll
    for (int l = 0; l < 2; l++) {
        int i = tid + l * 256;          // 0..511 float4 slots of B tile
        bk[l] = i >> 4;
        bn[l] = (i & 15) << 2;
    }

    float4 ra[4], rb[2];
    float c[2][4][4] = {};

    // prologue: load k-tile 0 into registers
    #pragma unroll
    for (int l = 0; l < 4; l++) {
        int gr = row0 + am[l];
        ra[l] = (gr < M) ? *(const float4*)(A + (size_t)gr * K + ak[l])
                         : make_float4(0.f, 0.f, 0.f, 0.f);
    }
    #pragma unroll
    for (int l = 0; l < 2; l++)
        rb[l] = *(const float4*)(W + (size_t)bk[l] * 64 + bn[l]);

    constexpr int NT = K / 32;
    #pragma unroll
    for (int kt = 0; kt < NT; kt++) {
        // commit current registers to smem (tf32 convert at store)
        #pragma unroll
        for (int l = 0; l < 4; l++)
            *(uint4*)&As[am[l]][ak[l]] = cvt4(ra[l]);
        #pragma unroll
        for (int l = 0; l < 2; l++)
            *(uint4*)&Bs[bk[l]][bn[l]] = cvt4(rb[l]);
        __syncthreads();

        // prefetch next k-tile (LDGs overlap the MMA block below)
        if (kt + 1 < NT) {
            int k0 = (kt + 1) * 32;
            #pragma unroll
            for (int l = 0; l < 4; l++) {
                int gr = row0 + am[l];
                ra[l] = (gr < M) ? *(const float4*)(A + (size_t)gr * K + k0 + ak[l])
                                 : make_float4(0.f, 0.f, 0.f, 0.f);
            }
            #pragma unroll
            for (int l = 0; l < 2; l++)
                rb[l] = *(const float4*)(W + (size_t)(k0 + bk[l]) * 64 + bn[l]);
        }

        #pragma unroll
        for (int kc = 0; kc < 4; kc++) {
            int kb = kc * 8;
            uint32_t a[2][4];
            #pragma unroll
            for (int mt = 0; mt < 2; mt++) {
                int mb = wm * 32 + mt * 16;
                a[mt][0] = As[mb + g     ][kb + t    ];
                a[mt][1] = As[mb + g + 8 ][kb + t    ];
                a[mt][2] = As[mb + g     ][kb + t + 4];
                a[mt][3] = As[mb + g + 8 ][kb + t + 4];
            }
            uint32_t bfr[4][2];
            #pragma unroll
            for (int j = 0; j < 4; j++) {
                int nb = wn * 32 + j * 8;
                bfr[j][0] = Bs[kb + t    ][nb + g];
                bfr[j][1] = Bs[kb + t + 4][nb + g];
            }
            #pragma unroll
            for (int mt = 0; mt < 2; mt++) {
                #pragma unroll
                for (int j = 0; j < 4; j++) {
                    asm volatile(
                        "mma.sync.aligned.m16n8k8.row.col.f32.tf32.tf32.f32 "
                        "{%0,%1,%2,%3}, {%4,%5,%6,%7}, {%8,%9}, {%0,%1,%2,%3};"
                        : "+f"(c[mt][j][0]), "+f"(c[mt][j][1]),
                          "+f"(c[mt][j][2]), "+f"(c[mt][j][3])
                        : "r"(a[mt][0]), "r"(a[mt][1]), "r"(a[mt][2]), "r"(a[mt][3]),
                          "r"(bfr[j][0]), "r"(bfr[j][1]));
                }
            }
        }
        __syncthreads();
    }

    // epilogue: c0,c1 -> row g; c2,c3 -> row g+8; cols 2t, 2t+1
    #pragma unroll
    for (int mt = 0; mt < 2; mt++) {
        int r0 = row0 + wm * 32 + mt * 16 + g;
        float d0 = (SCALED && r0 < M)     ? dinv[r0]     : 1.0f;
        float d1 = (SCALED && r0 + 8 < M) ? dinv[r0 + 8] : 1.0f;
        #pragma unroll
        for (int j = 0; j < 4; j++) {
            int col = wn * 32 + j * 8 + 2 * t;
            if (r0 < M)
                *(float2*)(out + (size_t)r0 * 64 + col) =
                    make_float2(c[mt][j][0] * d0, c[mt][j][1] * d0);
            if (r0 + 8 < M)
                *(float2*)(out + (size_t)(r0 + 8) * 64 + col) =
                    make_float2(c[mt][j][2] * d1, c[mt][j][3] * d1);
        }
    }
}

// -------------------- pull aggregation + fused epilogue (64 features) --------------------
// 16 threads per node, 4 features each; 4 independent gathers in flight.
// NSCALE=true:  h is UNSCALED (layer 1): neighbor rows scaled by dinv[u], self by dinv[node].
// FUSE3=true:   instead of writing the relu'd row to `out`, immediately compute
//               h3[node][0:2] = (row @ W3) * dinv[node] via 16-lane shfl reduction.
template <bool NSCALE, bool FUSE3>
__global__ void k_pull64(const int* __restrict__ rstart, const int* __restrict__ degi,
                         const int* __restrict__ csr, const float* __restrict__ h,
                         const float* __restrict__ dinv, const float* __restrict__ b,
                         const float* __restrict__ W3, float* __restrict__ out,
                         float* __restrict__ h3, int n) {
    int gid  = blockIdx.x * blockDim.x + threadIdx.x;
    int node = gid >> 4;
    if (node >= n) return;
    int lane16 = gid & 15;
    int c = lane16 << 2;

    int s0  = __ldg(&rstart[node]);
    int cnt = __ldg(&degi[node]);
    float dn = dinv[node];

    float4 acc = *(const float4*)(h + (size_t)node * 64 + c);   // self-loop term
    if (NSCALE) { acc.x *= dn; acc.y *= dn; acc.z *= dn; acc.w *= dn; }

    int e = 0;
    for (; e + 4 <= cnt; e += 4) {
        int u0 = __ldg(&csr[s0 + e + 0]);
        int u1 = __ldg(&csr[s0 + e + 1]);
        int u2 = __ldg(&csr[s0 + e + 2]);
        int u3 = __ldg(&csr[s0 + e + 3]);
        float4 v0 = *(const float4*)(h + (size_t)u0 * 64 + c);
        float4 v1 = *(const float4*)(h + (size_t)u1 * 64 + c);
        float4 v2 = *(const float4*)(h + (size_t)u2 * 64 + c);
        float4 v3 = *(const float4*)(h + (size_t)u3 * 64 + c);
        if (NSCALE) {
            float d0 = __ldg(&dinv[u0]), d1 = __ldg(&dinv[u1]);
            float d2 = __ldg(&dinv[u2]), d3 = __ldg(&dinv[u3]);
            acc.x += v0.x * d0 + v1.x * d1 + v2.x * d2 + v3.x * d3;
            acc.y += v0.y * d0 + v1.y * d1 + v2.y * d2 + v3.y * d3;
            acc.z += v0.z * d0 + v1.z * d1 + v2.z * d2 + v3.z * d3;
            acc.w += v0.w * d0 + v1.w * d1 + v2.w * d2 + v3.w * d3;
        } else {
            acc.x += v0.x + v1.x + v2.x + v3.x;
            acc.y += v0.y + v1.y + v2.y + v3.y;
            acc.z += v0.z + v1.z + v2.z + v3.z;
            acc.w += v0.w + v1.w + v2.w + v3.w;
        }
    }
    for (; e < cnt; e++) {
        int u = __ldg(&csr[s0 + e]);
        float4 v = *(const float4*)(h + (size_t)u * 64 + c);
        float d = NSCALE ? __ldg(&dinv[u]) : 1.0f;
        acc.x += v.x * d; acc.y += v.y * d; acc.z += v.z * d; acc.w += v.w * d;
    }

    float4 bb = *(const float4*)(b + c);
    float4 o;
    o.x = fmaxf(dn * acc.x + bb.x, 0.f);
    o.y = fmaxf(dn * acc.y + bb.y, 0.f);
    o.z = fmaxf(dn * acc.z + bb.z, 0.f);
    o.w = fmaxf(dn * acc.w + bb.w, 0.f);

    if (!FUSE3) {
        *(float4*)(out + (size_t)node * 64 + c) = o;
    } else {
        // h3[node][j] = dinv[node] * sum_k row[k] * W3[k*2+j]
        float4 w0 = *(const float4*)(W3 + c * 2);       // W3[(c..c+1), (0..1)]
        float4 w1 = *(const float4*)(W3 + c * 2 + 4);   // W3[(c+2..c+3), (0..1)]
        float p0 = o.x * w0.x + o.y * w0.z + o.z * w1.x + o.w * w1.z;
        float p1 = o.x * w0.y + o.y * w0.w + o.z * w1.y + o.w * w1.w;
        unsigned hm = 0xFFFFu << (threadIdx.x & 16);
        #pragma unroll
        for (int off = 8; off > 0; off >>= 1) {
            p0 += __shfl_xor_sync(hm, p0, off, 16);
            p1 += __shfl_xor_sync(hm, p1, off, 16);
        }
        if (lane16 == 0) {
            h3[2 * (size_t)node + 0] = p0 * dn;
            h3[2 * (size_t)node + 1] = p1 * dn;
        }
    }
}

// -------------------- layer 3: pull (2 feats) + log_softmax, 1 thread/node --------------------
__global__ void k_pull2_final(const int* __restrict__ rstart, const int* __restrict__ degi,
                              const int* __restrict__ csr, const float* __restrict__ h3,
                              const float* __restrict__ dinv, const float* __restrict__ b3,
                              float* __restrict__ out, int n) {
    int i = blockIdx.x * blockDim.x + threadIdx.x;
    if (i >= n) return;
    int s0  = __ldg(&rstart[i]);
    int cnt = __ldg(&degi[i]);

    float2 self = *(const float2*)(h3 + (size_t)i * 2);
    float a0 = self.x, a1 = self.y;

    int e = 0;
    for (; e + 4 <= cnt; e += 4) {
        int u0 = __ldg(&csr[s0 + e + 0]);
        int u1 = __ldg(&csr[s0 + e + 1]);
        int u2 = __ldg(&csr[s0 + e + 2]);
        int u3 = __ldg(&csr[s0 + e + 3]);
        float2 v0 = *(const float2*)(h3 + (size_t)u0 * 2);
        float2 v1 = *(const float2*)(h3 + (size_t)u1 * 2);
        float2 v2 = *(const float2*)(h3 + (size_t)u2 * 2);
        float2 v3 = *(const float2*)(h3 + (size_t)u3 * 2);
        a0 += v0.x + v1.x + v2.x + v3.x;
        a1 += v0.y + v1.y + v2.y + v3.y;
    }
    for (; e < cnt; e++) {
        int u = __ldg(&csr[s0 + e]);
        float2 v = *(const float2*)(h3 + (size_t)u * 2);
        a0 += v.x; a1 += v.y;
    }

    float d  = dinv[i];
    float o0 = d * a0 + b3[0];
    float o1 = d * a1 + b3[1];
    float m  = fmaxf(o0, o1);
    float lse = m + logf(expf(o0 - m) + expf(o1 - m));
    out[2 * i + 0] = o0 - lse;
    out[2 * i + 1] = o1 - lse;
}

// -------------------- launch (single stream, serial) --------------------
extern "C" void kernel_launch(void* const* d_in, const int* in_sizes, int n_in,
                              void* d_out, int out_size) {
    const float* x  = (const float*)d_in[0];
    const int*   ei = (const int*)  d_in[1];
    const float* W1 = (const float*)d_in[2];
    const float* b1 = (const float*)d_in[3];
    const float* W2 = (const float*)d_in[4];
    const float* b2 = (const float*)d_in[5];
    const float* W3 = (const float*)d_in[6];
    const float* b3 = (const float*)d_in[7];

    const int N = in_sizes[0] / F_IN;
    const int E = in_sizes[1] / 2;
    const int* src = ei;
    const int* dst = ei + E;

    int *degi, *rstart, *cursor, *bsum, *csr;
    float *dinv, *h, *x2, *h3;
    cudaGetSymbolAddress((void**)&degi,   g_degi);
    cudaGetSymbolAddress((void**)&rstart, g_rstart);
    cudaGetSymbolAddress((void**)&cursor, g_cursor);
    cudaGetSymbolAddress((void**)&bsum,   g_bsum);
    cudaGetSymbolAddress((void**)&csr,    g_csr);
    cudaGetSymbolAddress((void**)&dinv,   g_dinv);
    cudaGetSymbolAddress((void**)&h,      g_h);
    cudaGetSymbolAddress((void**)&x2,     g_x2);
    cudaGetSymbolAddress((void**)&h3,     g_h3);

    const int T  = 256;
    const int NB = (N + 255) / 256;
    const int gemm_blocks = (N + 127) / 128;
    const int pull_blocks = (N * 16 + T - 1) / T;

    // prep start (independent of gemm1)
    k_zero_deg  <<<(N + T - 1) / T, T>>>(degi, N);
    k_count_deg <<<(E + T - 1) / T, T>>>(dst, degi, E);
    k_scan_block<<<NB, 256>>>(degi, rstart, bsum, N);

    // layer-1 GEMM (tf32 tc, UNSCALED) — submission 4 = ncu slot
    k_gemm_tc<F_IN, false><<<gemm_blocks, T>>>(x, W1, nullptr, h, N);

    // prep finish (scan_sums folded into add_off)
    k_add_off   <<<NB, 256>>>(rstart, cursor, bsum, degi, dinv, N);
    k_build_csr <<<(E + T - 1) / T, T>>>(src, dst, cursor, csr, E);

    // ---- layer 1 aggregation (neighbor-scaled pull) ----
    k_pull64<true, false><<<pull_blocks, T>>>(rstart, degi, csr, h, dinv, b1,
                                              nullptr, x2, nullptr, N);

    // ---- layer 2 (tf32 tc, dinv-scaled) + pull with fused layer-3 linear ----
    k_gemm_tc<HID, true><<<gemm_blocks, T>>>(x2, W2, dinv, h, N);
    k_pull64<false, true><<<pull_blocks, T>>>(rstart, degi, csr, h, dinv, b2,
                                              W3, nullptr, h3, N);

    // ---- layer 3 aggregation + log_softmax ----
    k_pull2_final<<<(N + T - 1) / T, T>>>(rstart, degi, csr, h3, dinv, b3, (float*)d_out, N);
}